// round 6
// baseline (speedup 1.0000x reference)
#include <cuda_runtime.h>
#include <cstdint>
#include <cstddef>

// Problem constants (fixed-shape problem):
//   grad_last: (B=8, M=4096) float32
//   indices:   (M=4096,) int32, values in [0, N=2048)
//   out:       (8, 4096, 2048) float32  -> 256 MB
//
// out[b, i, j] = (j == indices[i]) ? grad_last[b, i] : 0
//
// One block (128 threads) per output row (2048 floats = 8 KB).
// Each thread writes 2 x 32B via 256-bit stores (STG.E.256, sm_100+),
// streaming hint (.cs). Row is covered by 256 contiguous 32B chunks.

static constexpr unsigned B_DIM = 8;
static constexpr unsigned M_DIM = 4096;
static constexpr unsigned ROWS  = B_DIM * M_DIM;   // 32768 blocks
static constexpr unsigned CHUNKS_PER_ROW = 256;    // 2048 floats / 8

__global__ void __launch_bounds__(128)
reduce_max_grad_scatter(const float* __restrict__ grad_last,
                        const int* __restrict__ indices,
                        float* __restrict__ out)
{
    const unsigned row = blockIdx.x;          // b*4096 + i
    const unsigned i   = row & (M_DIM - 1u);
    const unsigned b   = row >> 12;
    const unsigned tid = threadIdx.x;

    // Block-uniform loads -> L1 broadcast hits.
    const unsigned ind = (unsigned)__ldg(&indices[i]);
    const float    g   = __ldg(&grad_last[b * M_DIM + i]);

    const unsigned hot = ind >> 3;            // which 8-float chunk holds the value
    const unsigned sub = ind & 7u;            // position within the chunk

    float* o = out + (size_t)row * 2048u + tid * 8u;

#pragma unroll
    for (int j = 0; j < 2; j++) {
        const unsigned c = j * 128u + tid;    // chunk id within the row
        float f0 = 0.f, f1 = 0.f, f2 = 0.f, f3 = 0.f;
        float f4 = 0.f, f5 = 0.f, f6 = 0.f, f7 = 0.f;
        if (c == hot) {                       // exactly 1 of 256 chunks per row
            f0 = (sub == 0u) ? g : 0.f;
            f1 = (sub == 1u) ? g : 0.f;
            f2 = (sub == 2u) ? g : 0.f;
            f3 = (sub == 3u) ? g : 0.f;
            f4 = (sub == 4u) ? g : 0.f;
            f5 = (sub == 5u) ? g : 0.f;
            f6 = (sub == 6u) ? g : 0.f;
            f7 = (sub == 7u) ? g : 0.f;
        }
        // 256-bit streaming store (STG.E.256 on sm_100+)
        asm volatile(
            "st.global.cs.v8.f32 [%0], {%1,%2,%3,%4,%5,%6,%7,%8};"
            :: "l"(o + j * 1024u),
               "f"(f0), "f"(f1), "f"(f2), "f"(f3),
               "f"(f4), "f"(f5), "f"(f6), "f"(f7)
            : "memory");
    }
}

extern "C" void kernel_launch(void* const* d_in, const int* in_sizes, int n_in,
                              void* d_out, int out_size)
{
    const float* grad    = (const float*)d_in[0];
    const int*   indices = (const int*)d_in[1];
    float*       out     = (float*)d_out;

    (void)in_sizes; (void)n_in; (void)out_size;

    reduce_max_grad_scatter<<<ROWS, 128>>>(grad, indices, out);
}

// round 7
// speedup vs baseline: 1.0236x; 1.0236x over previous
#include <cuda_runtime.h>
#include <cstdint>
#include <cstddef>

// Problem constants (fixed-shape problem):
//   grad_last: (B=8, M=4096) float32
//   indices:   (M=4096,) int32, values in [0, N=2048)
//   out:       (8, 4096, 2048) float32  -> 256 MB, 16,777,216 float4
//
// out[b, i, j] = (j == indices[i]) ? grad_last[b, i] : 0
//
// Long-slab schedule: 2048 blocks x 256 threads, each block owns a
// CONTIGUOUS 8192-float4 (128 KB) slab and walks it in 32 coalesced
// iterations (block covers 4 KB per iteration). Goal: long same-row DRAM
// bursts per bank -> fewer activate/precharge stalls vs 32768 tiny slabs.

static constexpr unsigned M_DIM     = 4096;
static constexpr unsigned TOTAL_VEC = 16777216u;   // 8*4096*512
static constexpr unsigned GRID      = 2048;
static constexpr unsigned BLOCK     = 256;
static constexpr unsigned ITERS     = TOTAL_VEC / (GRID * BLOCK);  // 32
static constexpr unsigned VEC_PER_BLOCK = BLOCK * ITERS;           // 8192

__global__ void __launch_bounds__(BLOCK)
reduce_max_grad_scatter(const float* __restrict__ grad_last,
                        const int* __restrict__ indices,
                        float4* __restrict__ out)
{
    const unsigned base = blockIdx.x * VEC_PER_BLOCK + threadIdx.x;

#pragma unroll
    for (unsigned it = 0; it < ITERS; it++) {
        const unsigned idx = base + it * BLOCK;   // global float4 index
        const unsigned row = idx >> 9;            // b*4096 + i
        const unsigned q   = idx & 511u;          // float4 slot within row
        const unsigned i   = row & (M_DIM - 1u);

        // Warp-uniform (256 consecutive idx share the same half-row) -> L1 bcast
        const unsigned ind = (unsigned)__ldg(&indices[i]);

        float4 v = make_float4(0.f, 0.f, 0.f, 0.f);
        if ((ind >> 2) == q) {                    // 1-in-512 slots per row
            const unsigned b = row >> 12;
            const float g = __ldg(&grad_last[b * M_DIM + i]);
            const unsigned lane = ind & 3u;
            v.x = (lane == 0u) ? g : 0.f;
            v.y = (lane == 1u) ? g : 0.f;
            v.z = (lane == 2u) ? g : 0.f;
            v.w = (lane == 3u) ? g : 0.f;
        }
        __stcs(&out[idx], v);                     // streaming 128-bit store
    }
}

extern "C" void kernel_launch(void* const* d_in, const int* in_sizes, int n_in,
                              void* d_out, int out_size)
{
    const float* grad    = (const float*)d_in[0];
    const int*   indices = (const int*)d_in[1];
    float4*      out     = (float4*)d_out;

    (void)in_sizes; (void)n_in; (void)out_size;

    reduce_max_grad_scatter<<<GRID, BLOCK>>>(grad, indices, out);
}